// round 15
// baseline (speedup 1.0000x reference)
#include <cuda_runtime.h>
#include <cuda_bf16.h>
#include <mma.h>
#include <cstdint>

using namespace nvcuda;

#define NN 100000
#define NPAD 100096   // 782 * 128, lets GEMM store unguarded into scratch buffers
#define EE 1600000
#define DD 256
#define OUTC 128
#define EPSV 1e-5f

// ---------------- scratch (static device globals; no allocation) ----------------
__device__ float d_z[(size_t)NPAD * DD];
__device__ float d_h[(size_t)NPAD * DD];
__device__ float d_q[(size_t)NPAD * DD];
__device__ float d_k[(size_t)NPAD * DD];
__device__ float d_v[(size_t)NPAD * DD];
__device__ float d_num[(size_t)NPAD * DD];
__device__ float d_x1[(size_t)NPAD * DD];
__device__ float d_g0[(size_t)NPAD * DD];
__device__ float d_agg[(size_t)NPAD * DD];
__device__ float d_tail[128 * 256];    // tail spill for GEMMs writing exact-size outputs

__device__ float d_kvs[DD * DD];
__device__ float d_ksum[DD];
__device__ float d_vsum[DD];
__device__ float d_denom[NN];
__device__ float d_deg[NN];
__device__ float d_rsq[NN];
__device__ float d_s1a[DD], d_s2a[DD], d_sc0[DD], d_sh0[DD];
__device__ float d_s1b[DD], d_s2b[DD], d_sc1[DD], d_sh1[DD];

// converted weights: [slot][n*256 + k], transposed (Wt[n][k] = W[k][n]), hi/lo bf16 split
__device__ __nv_bfloat16 d_wth[8][256 * 256];
__device__ __nv_bfloat16 d_wtl[8][256 * 256];

// ---------------- utility ----------------
__device__ __forceinline__ float warp_sum(float v) {
#pragma unroll
    for (int o = 16; o; o >>= 1) v += __shfl_xor_sync(0xffffffffu, v, o);
    return v;
}

// ---------------- zero accumulators (graph replays: must run every launch) ----------------
__global__ void zero_kernel() {
    size_t stride = (size_t)gridDim.x * blockDim.x;
    size_t i0 = (size_t)blockIdx.x * blockDim.x + threadIdx.x;
    for (size_t i = i0; i < (size_t)NN * DD; i += stride) d_agg[i] = 0.f;
    for (size_t i = i0; i < (size_t)NN; i += stride) d_deg[i] = 0.f;
    for (size_t i = i0; i < (size_t)DD * DD; i += stride) d_kvs[i] = 0.f;
    for (size_t i = i0; i < (size_t)DD; i += stride) {
        d_ksum[i] = 0.f; d_vsum[i] = 0.f;
        d_s1a[i] = 0.f; d_s2a[i] = 0.f;
        d_s1b[i] = 0.f; d_s2b[i] = 0.f;
    }
}

// ---------------- weight convert: W[K=256, NC] fp32 -> Wt hi/lo bf16 [NC, 256] ----------------
__global__ void wconv_kernel(const float* __restrict__ W, int NC,
                             __nv_bfloat16* __restrict__ hi, __nv_bfloat16* __restrict__ lo)
{
    int n = blockIdx.x;       // 0..NC-1
    int k = threadIdx.x;      // 0..255
    float w = W[(size_t)k * NC + n];
    __nv_bfloat16 h = __float2bfloat16(w);
    hi[(size_t)n * 256 + k] = h;
    lo[(size_t)n * 256 + k] = __float2bfloat16(w - __bfloat162float(h));
}

// ---------------- wmma bf16 split GEMM: C = A[M,256] @ W[256,NC] + bscale*bias -------------
// Wt transposed hi/lo bf16 [NC, 256]. Block 128x128, BK=32, 8 warps (4M x 2N), warp 32x64.
// acc = Ah*Bh + Ah*Bl + Al*Bh  (drops lo*lo term: rel err ~2^-17).
// R13 proven config: single-buffer staging, grid x = M-tile (fast), y = N-tile.
// MODE 0: A read directly.  MODE 1: A := 0.8*(relu(zA*sc+sh)+gA)+0.2*xA (fused combine).
#define LDA 40   // smem leading dim (bf16 elems), mult of 8
#define LDB 136  // bias panel leading dim (fp32), mult of 4

typedef wmma::fragment<wmma::matrix_a, 16, 16, 16, __nv_bfloat16, wmma::row_major> FragA;
typedef wmma::fragment<wmma::matrix_a, 16, 16, 16, __nv_bfloat16, wmma::col_major> FragAT;
typedef wmma::fragment<wmma::matrix_b, 16, 16, 16, __nv_bfloat16, wmma::col_major> FragB;
typedef wmma::fragment<wmma::matrix_b, 16, 16, 16, __nv_bfloat16, wmma::row_major> FragBT;
typedef wmma::fragment<wmma::accumulator, 16, 16, 16, float> FragC;

template <int MODE>
__global__ __launch_bounds__(256, 2)
void tgemm_kernel(const float* __restrict__ A,
                  const __nv_bfloat16* __restrict__ Wth,
                  const __nv_bfloat16* __restrict__ Wtl,
                  const float* __restrict__ bias, float bscale,
                  float* __restrict__ C, int M, int Mstore, int NC,
                  float* __restrict__ tailbuf,
                  const float* __restrict__ gA, const float* __restrict__ xA,
                  const float* __restrict__ scA, const float* __restrict__ shA)
{
    extern __shared__ char smc[];
    __nv_bfloat16* Ah = (__nv_bfloat16*)smc;                   // 128*40*2 = 10240
    __nv_bfloat16* Al = (__nv_bfloat16*)(smc + 10240);
    __nv_bfloat16* Bh = (__nv_bfloat16*)(smc + 20480);
    __nv_bfloat16* Bl = (__nv_bfloat16*)(smc + 30720);
    float*         brep = (float*)(smc + 40960);               // 16*136*4 = 8704

    int tid = threadIdx.x;
    int wid = tid >> 5;
    int wm = wid & 3;          // 0..3 -> M offset wm*32
    int wn = wid >> 2;         // 0..1 -> N offset wn*64
    int row0 = blockIdx.x * 128;
    int n0 = blockIdx.y * 128;

    // bias replicated over 16 rows (acc init via load_matrix_sync)
    for (int i = tid; i < 16 * LDB; i += 256) {
        int c = i % LDB;
        brep[i] = (c < 128) ? bscale * bias[n0 + c] : 0.f;
    }
    __syncthreads();

    FragC acc[2][4];
#pragma unroll
    for (int mi = 0; mi < 2; mi++)
#pragma unroll
        for (int ni = 0; ni < 4; ni++)
            wmma::load_matrix_sync(acc[mi][ni], brep + wn * 64 + ni * 16, LDB,
                                   wmma::mem_row_major);

    for (int kc = 0; kc < 8; kc++) {
        __syncthreads();
        // ---- stage A [128 rows x 32 k] fp32 -> hi/lo bf16 ----
#pragma unroll
        for (int i = 0; i < 4; i++) {
            int f = tid + i * 256;           // 0..1023
            int r = f >> 3;
            int c4 = (f & 7) * 4;
            float4 v = make_float4(0.f, 0.f, 0.f, 0.f);
            if (row0 + r < M) {
                size_t gi = (size_t)(row0 + r) * 256 + kc * 32 + c4;
                v = *(const float4*)(A + gi);
                if constexpr (MODE == 1) {
                    int col = kc * 32 + c4;
                    float4 gv = *(const float4*)(gA + gi);
                    float4 xv = *(const float4*)(xA + gi);
                    float4 scv = *(const float4*)(scA + col);
                    float4 shv = *(const float4*)(shA + col);
                    v.x = 0.8f * (fmaxf(v.x * scv.x + shv.x, 0.f) + gv.x) + 0.2f * xv.x;
                    v.y = 0.8f * (fmaxf(v.y * scv.y + shv.y, 0.f) + gv.y) + 0.2f * xv.y;
                    v.z = 0.8f * (fmaxf(v.z * scv.z + shv.z, 0.f) + gv.z) + 0.2f * xv.z;
                    v.w = 0.8f * (fmaxf(v.w * scv.w + shv.w, 0.f) + gv.w) + 0.2f * xv.w;
                }
            }
            __nv_bfloat162 h01 = __floats2bfloat162_rn(v.x, v.y);
            __nv_bfloat162 h23 = __floats2bfloat162_rn(v.z, v.w);
            float2 f01 = __bfloat1622float2(h01);
            float2 f23 = __bfloat1622float2(h23);
            __nv_bfloat162 l01 = __floats2bfloat162_rn(v.x - f01.x, v.y - f01.y);
            __nv_bfloat162 l23 = __floats2bfloat162_rn(v.z - f23.x, v.w - f23.y);
            *(__nv_bfloat162*)(Ah + r * LDA + c4)     = h01;
            *(__nv_bfloat162*)(Ah + r * LDA + c4 + 2) = h23;
            *(__nv_bfloat162*)(Al + r * LDA + c4)     = l01;
            *(__nv_bfloat162*)(Al + r * LDA + c4 + 2) = l23;
        }
        // ---- stage B [128 n x 32 k] hi/lo from preconverted Wt ----
#pragma unroll
        for (int i = 0; i < 2; i++) {
            int f = tid + i * 256;           // 0..511
            int r = f >> 2;
            int c = (f & 3) * 8;
            *(uint4*)(Bh + r * LDA + c) =
                *(const uint4*)(Wth + (size_t)(n0 + r) * 256 + kc * 32 + c);
            *(uint4*)(Bl + r * LDA + c) =
                *(const uint4*)(Wtl + (size_t)(n0 + r) * 256 + kc * 32 + c);
        }
        __syncthreads();

#pragma unroll
        for (int ks = 0; ks < 32; ks += 16) {
            FragA ah[2], al[2];
#pragma unroll
            for (int mi = 0; mi < 2; mi++) {
                wmma::load_matrix_sync(ah[mi], Ah + (wm * 32 + mi * 16) * LDA + ks, LDA);
                wmma::load_matrix_sync(al[mi], Al + (wm * 32 + mi * 16) * LDA + ks, LDA);
            }
#pragma unroll
            for (int ni = 0; ni < 4; ni++) {
                FragB bh, bl;
                wmma::load_matrix_sync(bh, Bh + (wn * 64 + ni * 16) * LDA + ks, LDA);
                wmma::load_matrix_sync(bl, Bl + (wn * 64 + ni * 16) * LDA + ks, LDA);
#pragma unroll
                for (int mi = 0; mi < 2; mi++) {
                    wmma::mma_sync(acc[mi][ni], ah[mi], bh, acc[mi][ni]);
                    wmma::mma_sync(acc[mi][ni], ah[mi], bl, acc[mi][ni]);
                    wmma::mma_sync(acc[mi][ni], al[mi], bh, acc[mi][ni]);
                }
            }
        }
    }

    if (row0 + 128 <= Mstore) {
#pragma unroll
        for (int mi = 0; mi < 2; mi++)
#pragma unroll
            for (int ni = 0; ni < 4; ni++)
                wmma::store_matrix_sync(
                    C + (size_t)(row0 + wm * 32 + mi * 16) * NC + n0 + wn * 64 + ni * 16,
                    acc[mi][ni], NC, wmma::mem_row_major);
    } else {
        // tail spill: only the last M-block of an exact-size output takes this path
#pragma unroll
        for (int mi = 0; mi < 2; mi++)
#pragma unroll
            for (int ni = 0; ni < 4; ni++)
                wmma::store_matrix_sync(
                    tailbuf + (size_t)(wm * 32 + mi * 16) * NC + n0 + wn * 64 + ni * 16,
                    acc[mi][ni], NC, wmma::mem_row_major);
        __syncthreads();
        int valid = Mstore - row0;
        for (int i = tid; i < valid * 128; i += 256) {
            int r = i >> 7;
            int c = i & 127;
            C[(size_t)(row0 + r) * NC + n0 + c] = tailbuf[(size_t)r * NC + n0 + c];
        }
    }
}

// ---------------- kvs = k^T @ v  [256,256] via wmma, split-L with atomics ----------------
// kvs[m][d] = sum_l k[l][m] * v[l][d]. A: col_major over sk[l][m] (m contiguous),
// B: row_major over sv[l][d]. 3-pass hi/lo split. CTA: 128x128 out tile, L-chunk 1024.
// Fused vsum: CTAs with m0==0 accumulate per-thread fp32 column partials of v and
// atomic-reduce into d_vsum (each thread owns 4 fixed columns).
#define KLD 136   // smem leading dim (bf16), mult of 8
#define KVCH 1024

__global__ __launch_bounds__(256, 2)
void kvs_wmma_kernel(const float* __restrict__ kk_, const float* __restrict__ vv_, int N)
{
    extern __shared__ char smk[];
    __nv_bfloat16* skh = (__nv_bfloat16*)smk;                    // 32*136*2 = 8704 each
    __nv_bfloat16* skl = skh + 32 * KLD;
    __nv_bfloat16* svh = skl + 32 * KLD;
    __nv_bfloat16* svl = svh + 32 * KLD;                         // 34816 total tiles
    float* stage = (float*)smk;                                  // epilogue reuse: 8*2048*4 = 64KB

    int tid = threadIdx.x;
    int wid = tid >> 5;
    int lane = tid & 31;
    int wm = wid & 3;
    int wn = wid >> 2;
    int m0 = (blockIdx.x >> 1) * 128;
    int d0 = (blockIdx.x & 1) * 128;
    int l0 = blockIdx.y * KVCH;
    int lend = min(l0 + KVCH, N);

    float vsum_acc[4] = {0.f, 0.f, 0.f, 0.f};

    FragC acc[2][4];
#pragma unroll
    for (int mi = 0; mi < 2; mi++)
#pragma unroll
        for (int ni = 0; ni < 4; ni++)
            wmma::fill_fragment(acc[mi][ni], 0.f);

    for (int lb = l0; lb < lend; lb += 32) {
        __syncthreads();
        // stage k [32 l x 128 m] and v [32 l x 128 d], fp32 -> hi/lo bf16
#pragma unroll
        for (int i = 0; i < 4; i++) {
            int f = tid + i * 256;            // 0..1023
            int l = f >> 5;
            int c4 = (f & 31) * 4;
            float4 kvv = make_float4(0.f, 0.f, 0.f, 0.f);
            float4 vvv = make_float4(0.f, 0.f, 0.f, 0.f);
            if (lb + l < N) {
                kvv = *(const float4*)(kk_ + (size_t)(lb + l) * 256 + m0 + c4);
                vvv = *(const float4*)(vv_ + (size_t)(lb + l) * 256 + d0 + c4);
            }
            vsum_acc[0] += vvv.x; vsum_acc[1] += vvv.y;
            vsum_acc[2] += vvv.z; vsum_acc[3] += vvv.w;
            __nv_bfloat162 kh01 = __floats2bfloat162_rn(kvv.x, kvv.y);
            __nv_bfloat162 kh23 = __floats2bfloat162_rn(kvv.z, kvv.w);
            float2 kf01 = __bfloat1622float2(kh01);
            float2 kf23 = __bfloat1622float2(kh23);
            __nv_bfloat162 kl01 = __floats2bfloat162_rn(kvv.x - kf01.x, kvv.y - kf01.y);
            __nv_bfloat162 kl23 = __floats2bfloat162_rn(kvv.z - kf23.x, kvv.w - kf23.y);
            *(__nv_bfloat162*)(skh + l * KLD + c4)     = kh01;
            *(__nv_bfloat162*)(skh + l * KLD + c4 + 2) = kh23;
            *(__nv_bfloat162*)(skl + l * KLD + c4)     = kl01;
            *(__nv_bfloat162*)(skl + l * KLD + c4 + 2) = kl23;
            __nv_bfloat162 vh01 = __floats2bfloat162_rn(vvv.x, vvv.y);
            __nv_bfloat162 vh23 = __floats2bfloat162_rn(vvv.z, vvv.w);
            float2 vf01 = __bfloat1622float2(vh01);
            float2 vf23 = __bfloat1622float2(vh23);
            __nv_bfloat162 vl01 = __floats2bfloat162_rn(vvv.x - vf01.x, vvv.y - vf01.y);
            __nv_bfloat162 vl23 = __floats2bfloat162_rn(vvv.z - vf23.x, vvv.w - vf23.y);
            *(__nv_bfloat162*)(svh + l * KLD + c4)     = vh01;
            *(__nv_bfloat162*)(svh + l * KLD + c4 + 2) = vh23;
            *(__nv_bfloat162*)(svl + l * KLD + c4)     = vl01;
            *(__nv_bfloat162*)(svl + l * KLD + c4 + 2) = vl23;
        }
        __syncthreads();

#pragma unroll
        for (int ks = 0; ks < 32; ks += 16) {
            FragAT ah[2], al[2];   // col_major: element (i,k) at ptr[i + k*KLD]
#pragma unroll
            for (int mi = 0; mi < 2; mi++) {
                wmma::load_matrix_sync(ah[mi], skh + ks * KLD + wm * 32 + mi * 16, KLD);
                wmma::load_matrix_sync(al[mi], skl + ks * KLD + wm * 32 + mi * 16, KLD);
            }
#pragma unroll
            for (int ni = 0; ni < 4; ni++) {
                FragBT bh, bl;     // row_major: element (k,j) at ptr[k*KLD + j]
                wmma::load_matrix_sync(bh, svh + ks * KLD + wn * 64 + ni * 16, KLD);
                wmma::load_matrix_sync(bl, svl + ks * KLD + wn * 64 + ni * 16, KLD);
#pragma unroll
                for (int mi = 0; mi < 2; mi++) {
                    wmma::mma_sync(acc[mi][ni], ah[mi], bh, acc[mi][ni]);
                    wmma::mma_sync(acc[mi][ni], ah[mi], bl, acc[mi][ni]);
                    wmma::mma_sync(acc[mi][ni], al[mi], bh, acc[mi][ni]);
                }
            }
        }
    }

    // fused vsum reduce (v tile is staged by both m0 blocks; only m0==0 contributes)
    if (m0 == 0) {
        int c4 = (tid & 31) * 4;
#pragma unroll
        for (int j = 0; j < 4; j++)
            atomicAdd(&d_vsum[d0 + c4 + j], vsum_acc[j]);
    }

    // epilogue: stage per-warp 32x64 then atomic-reduce into d_kvs
    __syncthreads();
    float* ws = stage + wid * 2048;
#pragma unroll
    for (int mi = 0; mi < 2; mi++)
#pragma unroll
        for (int ni = 0; ni < 4; ni++)
            wmma::store_matrix_sync(ws + (size_t)mi * 16 * 64 + ni * 16,
                                    acc[mi][ni], 64, wmma::mem_row_major);
    __syncwarp();
    int rbase = m0 + wm * 32;
    int cbase = d0 + wn * 64;
#pragma unroll
    for (int idx = 0; idx < 64; idx++) {
        int f = lane + idx * 32;      // 0..2047
        int r = f >> 6;
        int c = f & 63;
        atomicAdd(&d_kvs[(rbase + r) * 256 + cbase + c], ws[f]);
    }
}

// ---------------- column sums (colsum2 for BN stats) ----------------
__global__ void colsum2_kernel(const float* __restrict__ A, float* __restrict__ s1,
                               float* __restrict__ s2, int N)
{
    int col = threadIdx.x;
    int r0 = blockIdx.x * 500;
    int rend = min(r0 + 500, N);
    float s = 0.f, ss = 0.f;
    for (int r = r0; r < rend; r++) {
        float v = A[(size_t)r * 256 + col];
        s += v; ss += v * v;
    }
    atomicAdd(&s1[col], s);
    atomicAdd(&s2[col], ss);
}

// ---------------- per-row LayerNorm + ReLU ----------------
__global__ void ln_relu_kernel(const float* __restrict__ z, const float* __restrict__ g,
                               const float* __restrict__ b, float* __restrict__ out, int N)
{
    int row = blockIdx.x * 8 + (threadIdx.x >> 5);
    if (row >= N) return;
    int lane = threadIdx.x & 31;
    const float* zr = z + (size_t)row * 256;
    float v[8];
    float s = 0.f;
#pragma unroll
    for (int i = 0; i < 8; i++) { v[i] = zr[lane + 32 * i]; s += v[i]; }
    s = warp_sum(s);
    float m = s * (1.f / 256.f);
    float ss = 0.f;
#pragma unroll
    for (int i = 0; i < 8; i++) { float dv = v[i] - m; ss += dv * dv; }
    ss = warp_sum(ss);
    float inv = rsqrtf(ss * (1.f / 256.f) + EPSV);
    float* outr = out + (size_t)row * 256;
#pragma unroll
    for (int i = 0; i < 8; i++) {
        int c = lane + 32 * i;
        float r = (v[i] - m) * inv * g[c] + b[c];
        outr[c] = fmaxf(r, 0.f);
    }
}

// ---------------- L2 row normalize k + fused colsum into d_ksum ----------------
// Per-warp: normalize row in registers, then per-lane partial colsum accumulated
// across the warp's row is atomically added once per row (8 atomics per lane-row).
// To cut atomic count 8x, accumulate across the 8 rows of the block in smem first.
__global__ void normcolsum_kernel(float* __restrict__ a, int N)
{
    __shared__ float scol[256];
    int tid = threadIdx.x;
    int row = blockIdx.x * 8 + (tid >> 5);
    int lane = tid & 31;
    if (tid < 256) scol[tid] = 0.f;
    __syncthreads();

    if (row < N) {
        float* ar = a + (size_t)row * 256;
        float v[8];
        float ss = 0.f;
#pragma unroll
        for (int i = 0; i < 8; i++) { v[i] = ar[lane + 32 * i]; ss += v[i] * v[i]; }
        ss = warp_sum(ss);
        float inv = rsqrtf(ss);
#pragma unroll
        for (int i = 0; i < 8; i++) {
            float nk = v[i] * inv;
            ar[lane + 32 * i] = nk;
            atomicAdd(&scol[lane + 32 * i], nk);   // smem atomic, spread addresses
        }
    }
    __syncthreads();
    if (tid < 256 && scol[tid] != 0.f) atomicAdd(&d_ksum[tid], scol[tid]);
}

// ---------------- L2 row normalize + fused denom = dot(q_norm, ksum) + 2n ----------------
__global__ void normdot_kernel(float* __restrict__ a, int N, float nf)
{
    int row = blockIdx.x * 8 + (threadIdx.x >> 5);
    if (row >= N) return;
    int lane = threadIdx.x & 31;
    float* ar = a + (size_t)row * 256;
    float v[8];
    float ss = 0.f;
#pragma unroll
    for (int i = 0; i < 8; i++) { v[i] = ar[lane + 32 * i]; ss += v[i] * v[i]; }
    ss = warp_sum(ss);
    float inv = rsqrtf(ss);
    float ds = 0.f;
#pragma unroll
    for (int i = 0; i < 8; i++) {
        float nq = v[i] * inv;
        ar[lane + 32 * i] = nq;
        ds += nq * d_ksum[lane + 32 * i];
    }
    ds = warp_sum(ds);
    if (lane == 0) d_denom[row] = ds + 2.f * nf;
}

// ---------------- attention epilogue (denom precomputed) ----------------
__global__ void attn_ln_kernel(const float* __restrict__ num,
                               const float* __restrict__ h,
                               const float* __restrict__ g, const float* __restrict__ b,
                               float* __restrict__ out, int N)
{
    int row = blockIdx.x * 8 + (threadIdx.x >> 5);
    if (row >= N) return;
    int lane = threadIdx.x & 31;
    size_t base = (size_t)row * 256;
    float rinv = 1.f / d_denom[row];

    float t[8];
    float s = 0.f;
#pragma unroll
    for (int i = 0; i < 8; i++) {
        int c = lane + 32 * i;
        t[i] = (num[base + c] * rinv + h[base + c]) * 0.5f;
        s += t[i];
    }
    s = warp_sum(s);
    float m = s * (1.f / 256.f);
    float ss = 0.f;
#pragma unroll
    for (int i = 0; i < 8; i++) { float dv = t[i] - m; ss += dv * dv; }
    ss = warp_sum(ss);
    float inv = rsqrtf(ss * (1.f / 256.f) + EPSV);
#pragma unroll
    for (int i = 0; i < 8; i++) {
        int c = lane + 32 * i;
        float r = (t[i] - m) * inv * g[c] + b[c];
        out[base + c] = fmaxf(r, 0.f);
    }
}

// ---------------- BN finalize ----------------
__global__ void bn_finalize_kernel(const float* __restrict__ s1, const float* __restrict__ s2,
                                   const float* __restrict__ g, const float* __restrict__ b,
                                   float* __restrict__ sc, float* __restrict__ sh, float n)
{
    int c = threadIdx.x;
    float m = s1[c] / n;
    float var = s2[c] / n - m * m;
    float scale = g[c] * rsqrtf(var + EPSV);
    sc[c] = scale;
    sh[c] = b[c] - m * scale;
}

// ---------------- BN apply + ReLU ----------------
__global__ void bn_relu_kernel(const float* __restrict__ z, const float* __restrict__ sc,
                               const float* __restrict__ sh, float* __restrict__ out)
{
    size_t i = (size_t)blockIdx.x * blockDim.x + threadIdx.x;
    if (i >= (size_t)NN * 64) return;
    float4 zv = ((const float4*)z)[i];
    int c4 = (int)(i & 63);
    float4 scv = ((const float4*)sc)[c4];
    float4 shv = ((const float4*)sh)[c4];
    float4 o;
    o.x = fmaxf(zv.x * scv.x + shv.x, 0.f);
    o.y = fmaxf(zv.y * scv.y + shv.y, 0.f);
    o.z = fmaxf(zv.z * scv.z + shv.z, 0.f);
    o.w = fmaxf(zv.w * scv.w + shv.w, 0.f);
    ((float4*)out)[i] = o;
}

// ---------------- degree / rsqrt ----------------
__global__ void deg_kernel(const int* __restrict__ col)
{
    int i = blockIdx.x * blockDim.x + threadIdx.x;
    if (i < EE) atomicAdd(&d_deg[col[i]], 1.f);
}

__global__ void rsq_kernel()
{
    int i = blockIdx.x * blockDim.x + threadIdx.x;
    if (i < NN) {
        float dgg = d_deg[i];
        d_rsq[i] = dgg > 0.f ? rsqrtf(dgg) : 0.f;
    }
}

// ---------------- edge scatter ----------------
__global__ void scatter_kernel(const int* __restrict__ rowi, const int* __restrict__ coli,
                               const float* __restrict__ g0, float* __restrict__ agg, int E)
{
    int e = blockIdx.x * 8 + (threadIdx.x >> 5);
    if (e >= E) return;
    int lane = threadIdx.x & 31;
    int r = __ldg(rowi + e);
    int c = __ldg(coli + e);
    float w = d_rsq[c] * d_rsq[r];
    const float4* gr = (const float4*)(g0 + (size_t)r * 256);
    float* ab = agg + (size_t)c * 256;
#pragma unroll
    for (int i = 0; i < 2; i++) {
        float4 gv = gr[lane + 32 * i];
        float* dst = ab + (size_t)(lane + 32 * i) * 4;
        asm volatile("red.global.add.v4.f32 [%0], {%1, %2, %3, %4};"
                     :: "l"(dst), "f"(gv.x * w), "f"(gv.y * w), "f"(gv.z * w), "f"(gv.w * w)
                     : "memory");
    }
}

// ---------------- host ----------------
extern "C" void kernel_launch(void* const* d_in, const int* in_sizes, int n_in,
                              void* d_out, int out_size)
{
    const float* x      = (const float*)d_in[0];
    const int*   ei     = (const int*)d_in[1];
    const float* tW0    = (const float*)d_in[2];
    const float* tb0    = (const float*)d_in[3];
    const float* tln0_g = (const float*)d_in[4];
    const float* tln0_b = (const float*)d_in[5];
    const float* Wq     = (const float*)d_in[6];
    const float* bq     = (const float*)d_in[7];
    const float* Wk     = (const float*)d_in[8];
    const float* bk     = (const float*)d_in[9];
    const float* Wv     = (const float*)d_in[10];
    const float* bv     = (const float*)d_in[11];
    const float* tln1_g = (const float*)d_in[12];
    const float* tln1_b = (const float*)d_in[13];
    const float* gW0    = (const float*)d_in[14];
    const float* gb0    = (const float*)d_in[15];
    const float* gbn0_g = (const float*)d_in[16];
    const float* gbn0_b = (const float*)d_in[17];
    const float* gWc    = (const float*)d_in[18];
    const float* gbc    = (const float*)d_in[19];
    const float* gbn1_g = (const float*)d_in[20];
    const float* gbn1_b = (const float*)d_in[21];
    const float* Wo     = (const float*)d_in[22];
    const float* bo     = (const float*)d_in[23];
    float* out = (float*)d_out;

    float *pz, *ph, *pq, *pk, *pv, *pnum, *px1, *pg0, *pagg, *ptail;
    float *pkvs, *pksum, *pvsum;
    float *ps1a, *ps2a, *psc0, *psh0, *ps1b, *ps2b, *psc1, *psh1;
    __nv_bfloat16 *pwth, *pwtl;
    cudaGetSymbolAddress((void**)&pz, d_z);
    cudaGetSymbolAddress((void**)&ph, d_h);
    cudaGetSymbolAddress((void**)&pq, d_q);
    cudaGetSymbolAddress((void**)&pk, d_k);
    cudaGetSymbolAddress((void**)&pv, d_v);
    cudaGetSymbolAddress((void**)&pnum, d_num);
    cudaGetSymbolAddress((void**)&px1, d_x1);
    cudaGetSymbolAddress((void**)&pg0, d_g0);
    cudaGetSymbolAddress((void**)&pagg, d_agg);
    cudaGetSymbolAddress((void**)&ptail, d_tail);
    cudaGetSymbolAddress((void**)&pkvs, d_kvs);
    cudaGetSymbolAddress((void**)&pksum, d_ksum);
    cudaGetSymbolAddress((void**)&pvsum, d_vsum);
    cudaGetSymbolAddress((void**)&ps1a, d_s1a);
    cudaGetSymbolAddress((void**)&ps2a, d_s2a);
    cudaGetSymbolAddress((void**)&psc0, d_sc0);
    cudaGetSymbolAddress((void**)&psh0, d_sh0);
    cudaGetSymbolAddress((void**)&ps1b, d_s1b);
    cudaGetSymbolAddress((void**)&ps2b, d_s2b);
    cudaGetSymbolAddress((void**)&psc1, d_sc1);
    cudaGetSymbolAddress((void**)&psh1, d_sh1);
    cudaGetSymbolAddress((void**)&pwth, d_wth);
    cudaGetSymbolAddress((void**)&pwtl, d_wtl);

    const int* rowi = ei;
    const int* coli = ei + EE;
    const float nf = (float)NN;

    const int TG_SMEM = 49664;  // 4*10240 (A/B hi/lo) + 8704 (bias panel)
    const int KV_SMEM = 65536;  // max(tiles 34816, epilogue staging 8*2048*4)
    cudaFuncSetAttribute(tgemm_kernel<0>, cudaFuncAttributeMaxDynamicSharedMemorySize, TG_SMEM);
    cudaFuncSetAttribute(tgemm_kernel<1>, cudaFuncAttributeMaxDynamicSharedMemorySize, TG_SMEM);
    cudaFuncSetAttribute(kvs_wmma_kernel, cudaFuncAttributeMaxDynamicSharedMemorySize, KV_SMEM);

    zero_kernel<<<512, 256>>>();

    // weight conversion (transposed hi/lo bf16)
    #define WSL(i) (pwth + (size_t)(i) * 256 * 256), (pwtl + (size_t)(i) * 256 * 256)
    wconv_kernel<<<256, 256>>>(tW0, 256, WSL(0));
    wconv_kernel<<<256, 256>>>(Wq,  256, WSL(1));
    wconv_kernel<<<256, 256>>>(Wk,  256, WSL(2));
    wconv_kernel<<<256, 256>>>(Wv,  256, WSL(3));
    wconv_kernel<<<256, 256>>>(gW0, 256, WSL(4));
    wconv_kernel<<<256, 256>>>(gWc, 256, WSL(5));
    wconv_kernel<<<128, 256>>>(Wo,  128, WSL(6));

    dim3 g2((NN + 127) / 128, 2);   // NC=256 GEMMs (R13 proven rasterization)
    dim3 g1((NN + 127) / 128, 1);   // NC=128 GEMM
    int rowgrid = (NN + 7) / 8;

    // ---- Transformer branch ----
    tgemm_kernel<0><<<g2, 256, TG_SMEM>>>(x, WSL(0), tb0, 1.f, pz, NN, NPAD, 256, ptail,
                                          nullptr, nullptr, nullptr, nullptr);
    ln_relu_kernel<<<rowgrid, 256>>>(pz, tln0_g, tln0_b, ph, NN);
    tgemm_kernel<0><<<g2, 256, TG_SMEM>>>(ph, WSL(1), bq, 1.f, pq, NN, NPAD, 256, ptail,
                                          nullptr, nullptr, nullptr, nullptr);
    tgemm_kernel<0><<<g2, 256, TG_SMEM>>>(ph, WSL(2), bk, 1.f, pk, NN, NPAD, 256, ptail,
                                          nullptr, nullptr, nullptr, nullptr);
    tgemm_kernel<0><<<g2, 256, TG_SMEM>>>(ph, WSL(3), bv, 1.f, pv, NN, NPAD, 256, ptail,
                                          nullptr, nullptr, nullptr, nullptr);
    normcolsum_kernel<<<rowgrid, 256>>>(pk, NN);      // normalize k + fused ksum
    normdot_kernel<<<rowgrid, 256>>>(pq, NN, nf);     // normalize q + fused denom
    kvs_wmma_kernel<<<dim3(4, (NN + KVCH - 1) / KVCH), 256, KV_SMEM>>>(pk, pv, NN);
    wconv_kernel<<<256, 256>>>(pkvs, 256, WSL(7));
    tgemm_kernel<0><<<g2, 256, TG_SMEM>>>(pq, WSL(7), pvsum, nf, pnum, NN, NPAD, 256, ptail,
                                          nullptr, nullptr, nullptr, nullptr);
    attn_ln_kernel<<<rowgrid, 256>>>(pnum, ph, tln1_g, tln1_b, px1, NN);

    // ---- GNN branch ----
    tgemm_kernel<0><<<g2, 256, TG_SMEM>>>(x, WSL(4), gb0, 1.f, pz, NN, NPAD, 256, ptail,
                                          nullptr, nullptr, nullptr, nullptr);
    colsum2_kernel<<<200, 256>>>(pz, ps1a, ps2a, NN);
    bn_finalize_kernel<<<1, 256>>>(ps1a, ps2a, gbn0_g, gbn0_b, psc0, psh0, nf);
    bn_relu_kernel<<<25000, 256>>>(pz, psc0, psh0, pg0);
    deg_kernel<<<(EE + 255) / 256, 256>>>(coli);
    rsq_kernel<<<(NN + 255) / 256, 256>>>();
    scatter_kernel<<<(EE + 7) / 8, 256>>>(rowi, coli, pg0, pagg, EE);
    tgemm_kernel<0><<<g2, 256, TG_SMEM>>>(pagg, WSL(5), gbc, 1.f, pz, NN, NPAD, 256, ptail,
                                          nullptr, nullptr, nullptr, nullptr);
    colsum2_kernel<<<200, 256>>>(pz, ps1b, ps2b, NN);
    bn_finalize_kernel<<<1, 256>>>(ps1b, ps2b, gbn1_g, gbn1_b, psc1, psh1, nf);

    // ---- output head: combine fused into final GEMM's A-staging (MODE=1) ----
    tgemm_kernel<1><<<g1, 256, TG_SMEM>>>(pz, WSL(6), bo, 1.f, out, NN, NN, 128, ptail,
                                          pg0, px1, psc1, psh1);
}

// round 16
// speedup vs baseline: 1.1023x; 1.1023x over previous
#include <cuda_runtime.h>
#include <cuda_bf16.h>
#include <mma.h>
#include <cstdint>

using namespace nvcuda;

#define NN 100000
#define NPAD 100096   // 782 * 128, lets GEMM store unguarded into scratch buffers
#define EE 1600000
#define DD 256
#define OUTC 128
#define EPSV 1e-5f

// ---------------- scratch (static device globals; no allocation) ----------------
__device__ float d_z[(size_t)NPAD * DD];
__device__ float d_zg[(size_t)NPAD * DD];   // GNN-branch private (stream overlap)
__device__ float d_h[(size_t)NPAD * DD];
__device__ float d_q[(size_t)NPAD * DD];
__device__ float d_k[(size_t)NPAD * DD];
__device__ float d_v[(size_t)NPAD * DD];
__device__ float d_num[(size_t)NPAD * DD];
__device__ float d_x1[(size_t)NPAD * DD];
__device__ float d_g0[(size_t)NPAD * DD];
__device__ float d_agg[(size_t)NPAD * DD];
__device__ float d_tail[128 * 256];    // tail spill for GEMMs writing exact-size outputs

__device__ float d_kvs[DD * DD];
__device__ float d_ksum[DD];
__device__ float d_vsum[DD];
__device__ float d_denom[NN];
__device__ float d_deg[NN];
__device__ float d_rsq[NN];
__device__ float d_s1a[DD], d_s2a[DD], d_sc0[DD], d_sh0[DD];
__device__ float d_s1b[DD], d_s2b[DD], d_sc1[DD], d_sh1[DD];

// converted weights: [slot][n*256 + k], transposed (Wt[n][k] = W[k][n]), hi/lo bf16 split
__device__ __nv_bfloat16 d_wth[8][256 * 256];
__device__ __nv_bfloat16 d_wtl[8][256 * 256];

// ---------------- utility ----------------
__device__ __forceinline__ float warp_sum(float v) {
#pragma unroll
    for (int o = 16; o; o >>= 1) v += __shfl_xor_sync(0xffffffffu, v, o);
    return v;
}

// ---------------- zero accumulators (graph replays: must run every launch) ----------------
__global__ void zero_kernel() {
    size_t stride = (size_t)gridDim.x * blockDim.x;
    size_t i0 = (size_t)blockIdx.x * blockDim.x + threadIdx.x;
    for (size_t i = i0; i < (size_t)NN * DD; i += stride) d_agg[i] = 0.f;
    for (size_t i = i0; i < (size_t)NN; i += stride) d_deg[i] = 0.f;
    for (size_t i = i0; i < (size_t)DD * DD; i += stride) d_kvs[i] = 0.f;
    for (size_t i = i0; i < (size_t)DD; i += stride) {
        d_ksum[i] = 0.f; d_vsum[i] = 0.f;
        d_s1a[i] = 0.f; d_s2a[i] = 0.f;
        d_s1b[i] = 0.f; d_s2b[i] = 0.f;
    }
}

// ---------------- weight convert: W[K=256, NC] fp32 -> Wt hi/lo bf16 [NC, 256] ----------------
__global__ void wconv_kernel(const float* __restrict__ W, int NC,
                             __nv_bfloat16* __restrict__ hi, __nv_bfloat16* __restrict__ lo)
{
    int n = blockIdx.x;       // 0..NC-1
    int k = threadIdx.x;      // 0..255
    float w = W[(size_t)k * NC + n];
    __nv_bfloat16 h = __float2bfloat16(w);
    hi[(size_t)n * 256 + k] = h;
    lo[(size_t)n * 256 + k] = __float2bfloat16(w - __bfloat162float(h));
}

// ---------------- wmma bf16 split GEMM: C = A[M,256] @ W[256,NC] + bscale*bias -------------
// Wt transposed hi/lo bf16 [NC, 256]. Block 128x128, BK=32, 8 warps (4M x 2N), warp 32x64.
// acc = Ah*Bh + Ah*Bl + Al*Bh  (drops lo*lo term: rel err ~2^-17).
// R13 proven config: single-buffer staging, grid x = M-tile (fast), y = N-tile.
// MODE 0: A read directly.  MODE 1: A := 0.8*(relu(zA*sc+sh)+gA)+0.2*xA (fused combine).
#define LDA 40   // smem leading dim (bf16 elems), mult of 8
#define LDB 136  // bias panel leading dim (fp32), mult of 4

typedef wmma::fragment<wmma::matrix_a, 16, 16, 16, __nv_bfloat16, wmma::row_major> FragA;
typedef wmma::fragment<wmma::matrix_a, 16, 16, 16, __nv_bfloat16, wmma::col_major> FragAT;
typedef wmma::fragment<wmma::matrix_b, 16, 16, 16, __nv_bfloat16, wmma::col_major> FragB;
typedef wmma::fragment<wmma::matrix_b, 16, 16, 16, __nv_bfloat16, wmma::row_major> FragBT;
typedef wmma::fragment<wmma::accumulator, 16, 16, 16, float> FragC;

template <int MODE>
__global__ __launch_bounds__(256, 2)
void tgemm_kernel(const float* __restrict__ A,
                  const __nv_bfloat16* __restrict__ Wth,
                  const __nv_bfloat16* __restrict__ Wtl,
                  const float* __restrict__ bias, float bscale,
                  float* __restrict__ C, int M, int Mstore, int NC,
                  float* __restrict__ tailbuf,
                  const float* __restrict__ gA, const float* __restrict__ xA,
                  const float* __restrict__ scA, const float* __restrict__ shA)
{
    extern __shared__ char smc[];
    __nv_bfloat16* Ah = (__nv_bfloat16*)smc;                   // 128*40*2 = 10240
    __nv_bfloat16* Al = (__nv_bfloat16*)(smc + 10240);
    __nv_bfloat16* Bh = (__nv_bfloat16*)(smc + 20480);
    __nv_bfloat16* Bl = (__nv_bfloat16*)(smc + 30720);
    float*         brep = (float*)(smc + 40960);               // 16*136*4 = 8704

    int tid = threadIdx.x;
    int wid = tid >> 5;
    int wm = wid & 3;          // 0..3 -> M offset wm*32
    int wn = wid >> 2;         // 0..1 -> N offset wn*64
    int row0 = blockIdx.x * 128;
    int n0 = blockIdx.y * 128;

    // bias replicated over 16 rows (acc init via load_matrix_sync)
    for (int i = tid; i < 16 * LDB; i += 256) {
        int c = i % LDB;
        brep[i] = (c < 128) ? bscale * bias[n0 + c] : 0.f;
    }
    __syncthreads();

    FragC acc[2][4];
#pragma unroll
    for (int mi = 0; mi < 2; mi++)
#pragma unroll
        for (int ni = 0; ni < 4; ni++)
            wmma::load_matrix_sync(acc[mi][ni], brep + wn * 64 + ni * 16, LDB,
                                   wmma::mem_row_major);

    for (int kc = 0; kc < 8; kc++) {
        __syncthreads();
        // ---- stage A [128 rows x 32 k] fp32 -> hi/lo bf16 ----
#pragma unroll
        for (int i = 0; i < 4; i++) {
            int f = tid + i * 256;           // 0..1023
            int r = f >> 3;
            int c4 = (f & 7) * 4;
            float4 v = make_float4(0.f, 0.f, 0.f, 0.f);
            if (row0 + r < M) {
                size_t gi = (size_t)(row0 + r) * 256 + kc * 32 + c4;
                v = *(const float4*)(A + gi);
                if constexpr (MODE == 1) {
                    int col = kc * 32 + c4;
                    float4 gv = *(const float4*)(gA + gi);
                    float4 xv = *(const float4*)(xA + gi);
                    float4 scv = *(const float4*)(scA + col);
                    float4 shv = *(const float4*)(shA + col);
                    v.x = 0.8f * (fmaxf(v.x * scv.x + shv.x, 0.f) + gv.x) + 0.2f * xv.x;
                    v.y = 0.8f * (fmaxf(v.y * scv.y + shv.y, 0.f) + gv.y) + 0.2f * xv.y;
                    v.z = 0.8f * (fmaxf(v.z * scv.z + shv.z, 0.f) + gv.z) + 0.2f * xv.z;
                    v.w = 0.8f * (fmaxf(v.w * scv.w + shv.w, 0.f) + gv.w) + 0.2f * xv.w;
                }
            }
            __nv_bfloat162 h01 = __floats2bfloat162_rn(v.x, v.y);
            __nv_bfloat162 h23 = __floats2bfloat162_rn(v.z, v.w);
            float2 f01 = __bfloat1622float2(h01);
            float2 f23 = __bfloat1622float2(h23);
            __nv_bfloat162 l01 = __floats2bfloat162_rn(v.x - f01.x, v.y - f01.y);
            __nv_bfloat162 l23 = __floats2bfloat162_rn(v.z - f23.x, v.w - f23.y);
            *(__nv_bfloat162*)(Ah + r * LDA + c4)     = h01;
            *(__nv_bfloat162*)(Ah + r * LDA + c4 + 2) = h23;
            *(__nv_bfloat162*)(Al + r * LDA + c4)     = l01;
            *(__nv_bfloat162*)(Al + r * LDA + c4 + 2) = l23;
        }
        // ---- stage B [128 n x 32 k] hi/lo from preconverted Wt ----
#pragma unroll
        for (int i = 0; i < 2; i++) {
            int f = tid + i * 256;           // 0..511
            int r = f >> 2;
            int c = (f & 3) * 8;
            *(uint4*)(Bh + r * LDA + c) =
                *(const uint4*)(Wth + (size_t)(n0 + r) * 256 + kc * 32 + c);
            *(uint4*)(Bl + r * LDA + c) =
                *(const uint4*)(Wtl + (size_t)(n0 + r) * 256 + kc * 32 + c);
        }
        __syncthreads();

#pragma unroll
        for (int ks = 0; ks < 32; ks += 16) {
            FragA ah[2], al[2];
#pragma unroll
            for (int mi = 0; mi < 2; mi++) {
                wmma::load_matrix_sync(ah[mi], Ah + (wm * 32 + mi * 16) * LDA + ks, LDA);
                wmma::load_matrix_sync(al[mi], Al + (wm * 32 + mi * 16) * LDA + ks, LDA);
            }
#pragma unroll
            for (int ni = 0; ni < 4; ni++) {
                FragB bh, bl;
                wmma::load_matrix_sync(bh, Bh + (wn * 64 + ni * 16) * LDA + ks, LDA);
                wmma::load_matrix_sync(bl, Bl + (wn * 64 + ni * 16) * LDA + ks, LDA);
#pragma unroll
                for (int mi = 0; mi < 2; mi++) {
                    wmma::mma_sync(acc[mi][ni], ah[mi], bh, acc[mi][ni]);
                    wmma::mma_sync(acc[mi][ni], ah[mi], bl, acc[mi][ni]);
                    wmma::mma_sync(acc[mi][ni], al[mi], bh, acc[mi][ni]);
                }
            }
        }
    }

    if (row0 + 128 <= Mstore) {
#pragma unroll
        for (int mi = 0; mi < 2; mi++)
#pragma unroll
            for (int ni = 0; ni < 4; ni++)
                wmma::store_matrix_sync(
                    C + (size_t)(row0 + wm * 32 + mi * 16) * NC + n0 + wn * 64 + ni * 16,
                    acc[mi][ni], NC, wmma::mem_row_major);
    } else {
        // tail spill: only the last M-block of an exact-size output takes this path
#pragma unroll
        for (int mi = 0; mi < 2; mi++)
#pragma unroll
            for (int ni = 0; ni < 4; ni++)
                wmma::store_matrix_sync(
                    tailbuf + (size_t)(wm * 32 + mi * 16) * NC + n0 + wn * 64 + ni * 16,
                    acc[mi][ni], NC, wmma::mem_row_major);
        __syncthreads();
        int valid = Mstore - row0;
        for (int i = tid; i < valid * 128; i += 256) {
            int r = i >> 7;
            int c = i & 127;
            C[(size_t)(row0 + r) * NC + n0 + c] = tailbuf[(size_t)r * NC + n0 + c];
        }
    }
}

// ---------------- kvs = k^T @ v  [256,256] via wmma, split-L with atomics ----------------
#define KLD 136   // smem leading dim (bf16), mult of 8
#define KVCH 1024

__global__ __launch_bounds__(256, 2)
void kvs_wmma_kernel(const float* __restrict__ kk_, const float* __restrict__ vv_, int N)
{
    extern __shared__ char smk[];
    __nv_bfloat16* skh = (__nv_bfloat16*)smk;                    // 32*136*2 = 8704 each
    __nv_bfloat16* skl = skh + 32 * KLD;
    __nv_bfloat16* svh = skl + 32 * KLD;
    __nv_bfloat16* svl = svh + 32 * KLD;                         // 34816 total tiles
    float* stage = (float*)smk;                                  // epilogue reuse: 8*2048*4 = 64KB

    int tid = threadIdx.x;
    int wid = tid >> 5;
    int lane = tid & 31;
    int wm = wid & 3;
    int wn = wid >> 2;
    int m0 = (blockIdx.x >> 1) * 128;
    int d0 = (blockIdx.x & 1) * 128;
    int l0 = blockIdx.y * KVCH;
    int lend = min(l0 + KVCH, N);

    float vsum_acc[4] = {0.f, 0.f, 0.f, 0.f};

    FragC acc[2][4];
#pragma unroll
    for (int mi = 0; mi < 2; mi++)
#pragma unroll
        for (int ni = 0; ni < 4; ni++)
            wmma::fill_fragment(acc[mi][ni], 0.f);

    for (int lb = l0; lb < lend; lb += 32) {
        __syncthreads();
#pragma unroll
        for (int i = 0; i < 4; i++) {
            int f = tid + i * 256;            // 0..1023
            int l = f >> 5;
            int c4 = (f & 31) * 4;
            float4 kvv = make_float4(0.f, 0.f, 0.f, 0.f);
            float4 vvv = make_float4(0.f, 0.f, 0.f, 0.f);
            if (lb + l < N) {
                kvv = *(const float4*)(kk_ + (size_t)(lb + l) * 256 + m0 + c4);
                vvv = *(const float4*)(vv_ + (size_t)(lb + l) * 256 + d0 + c4);
            }
            vsum_acc[0] += vvv.x; vsum_acc[1] += vvv.y;
            vsum_acc[2] += vvv.z; vsum_acc[3] += vvv.w;
            __nv_bfloat162 kh01 = __floats2bfloat162_rn(kvv.x, kvv.y);
            __nv_bfloat162 kh23 = __floats2bfloat162_rn(kvv.z, kvv.w);
            float2 kf01 = __bfloat1622float2(kh01);
            float2 kf23 = __bfloat1622float2(kh23);
            __nv_bfloat162 kl01 = __floats2bfloat162_rn(kvv.x - kf01.x, kvv.y - kf01.y);
            __nv_bfloat162 kl23 = __floats2bfloat162_rn(kvv.z - kf23.x, kvv.w - kf23.y);
            *(__nv_bfloat162*)(skh + l * KLD + c4)     = kh01;
            *(__nv_bfloat162*)(skh + l * KLD + c4 + 2) = kh23;
            *(__nv_bfloat162*)(skl + l * KLD + c4)     = kl01;
            *(__nv_bfloat162*)(skl + l * KLD + c4 + 2) = kl23;
            __nv_bfloat162 vh01 = __floats2bfloat162_rn(vvv.x, vvv.y);
            __nv_bfloat162 vh23 = __floats2bfloat162_rn(vvv.z, vvv.w);
            float2 vf01 = __bfloat1622float2(vh01);
            float2 vf23 = __bfloat1622float2(vh23);
            __nv_bfloat162 vl01 = __floats2bfloat162_rn(vvv.x - vf01.x, vvv.y - vf01.y);
            __nv_bfloat162 vl23 = __floats2bfloat162_rn(vvv.z - vf23.x, vvv.w - vf23.y);
            *(__nv_bfloat162*)(svh + l * KLD + c4)     = vh01;
            *(__nv_bfloat162*)(svh + l * KLD + c4 + 2) = vh23;
            *(__nv_bfloat162*)(svl + l * KLD + c4)     = vl01;
            *(__nv_bfloat162*)(svl + l * KLD + c4 + 2) = vl23;
        }
        __syncthreads();

#pragma unroll
        for (int ks = 0; ks < 32; ks += 16) {
            FragAT ah[2], al[2];   // col_major: element (i,k) at ptr[i + k*KLD]
#pragma unroll
            for (int mi = 0; mi < 2; mi++) {
                wmma::load_matrix_sync(ah[mi], skh + ks * KLD + wm * 32 + mi * 16, KLD);
                wmma::load_matrix_sync(al[mi], skl + ks * KLD + wm * 32 + mi * 16, KLD);
            }
#pragma unroll
            for (int ni = 0; ni < 4; ni++) {
                FragBT bh, bl;     // row_major: element (k,j) at ptr[k*KLD + j]
                wmma::load_matrix_sync(bh, svh + ks * KLD + wn * 64 + ni * 16, KLD);
                wmma::load_matrix_sync(bl, svl + ks * KLD + wn * 64 + ni * 16, KLD);
#pragma unroll
                for (int mi = 0; mi < 2; mi++) {
                    wmma::mma_sync(acc[mi][ni], ah[mi], bh, acc[mi][ni]);
                    wmma::mma_sync(acc[mi][ni], ah[mi], bl, acc[mi][ni]);
                    wmma::mma_sync(acc[mi][ni], al[mi], bh, acc[mi][ni]);
                }
            }
        }
    }

    // fused vsum reduce (v tile is staged by both m0 blocks; only m0==0 contributes)
    if (m0 == 0) {
        int c4 = (tid & 31) * 4;
#pragma unroll
        for (int j = 0; j < 4; j++)
            atomicAdd(&d_vsum[d0 + c4 + j], vsum_acc[j]);
    }

    // epilogue: stage per-warp 32x64 then atomic-reduce into d_kvs
    __syncthreads();
    float* ws = stage + wid * 2048;
#pragma unroll
    for (int mi = 0; mi < 2; mi++)
#pragma unroll
        for (int ni = 0; ni < 4; ni++)
            wmma::store_matrix_sync(ws + (size_t)mi * 16 * 64 + ni * 16,
                                    acc[mi][ni], 64, wmma::mem_row_major);
    __syncwarp();
    int rbase = m0 + wm * 32;
    int cbase = d0 + wn * 64;
#pragma unroll
    for (int idx = 0; idx < 64; idx++) {
        int f = lane + idx * 32;      // 0..2047
        int r = f >> 6;
        int c = f & 63;
        atomicAdd(&d_kvs[(rbase + r) * 256 + cbase + c], ws[f]);
    }
}

// ---------------- column sums ----------------
__global__ void colsum_kernel(const float* __restrict__ A, float* __restrict__ out, int N)
{
    int col = threadIdx.x;
    int r0 = blockIdx.x * 500;
    int rend = min(r0 + 500, N);
    float s = 0.f;
    for (int r = r0; r < rend; r++) s += A[(size_t)r * 256 + col];
    atomicAdd(&out[col], s);
}

__global__ void colsum2_kernel(const float* __restrict__ A, float* __restrict__ s1,
                               float* __restrict__ s2, int N)
{
    int col = threadIdx.x;
    int r0 = blockIdx.x * 500;
    int rend = min(r0 + 500, N);
    float s = 0.f, ss = 0.f;
    for (int r = r0; r < rend; r++) {
        float v = A[(size_t)r * 256 + col];
        s += v; ss += v * v;
    }
    atomicAdd(&s1[col], s);
    atomicAdd(&s2[col], ss);
}

// ---------------- per-row LayerNorm + ReLU ----------------
__global__ void ln_relu_kernel(const float* __restrict__ z, const float* __restrict__ g,
                               const float* __restrict__ b, float* __restrict__ out, int N)
{
    int row = blockIdx.x * 8 + (threadIdx.x >> 5);
    if (row >= N) return;
    int lane = threadIdx.x & 31;
    const float* zr = z + (size_t)row * 256;
    float v[8];
    float s = 0.f;
#pragma unroll
    for (int i = 0; i < 8; i++) { v[i] = zr[lane + 32 * i]; s += v[i]; }
    s = warp_sum(s);
    float m = s * (1.f / 256.f);
    float ss = 0.f;
#pragma unroll
    for (int i = 0; i < 8; i++) { float dv = v[i] - m; ss += dv * dv; }
    ss = warp_sum(ss);
    float inv = rsqrtf(ss * (1.f / 256.f) + EPSV);
    float* outr = out + (size_t)row * 256;
#pragma unroll
    for (int i = 0; i < 8; i++) {
        int c = lane + 32 * i;
        float r = (v[i] - m) * inv * g[c] + b[c];
        outr[c] = fmaxf(r, 0.f);
    }
}

// ---------------- L2 row normalize ----------------
__global__ void normalize_kernel(float* __restrict__ a, int N)
{
    int row = blockIdx.x * 8 + (threadIdx.x >> 5);
    if (row >= N) return;
    int lane = threadIdx.x & 31;
    float* ar = a + (size_t)row * 256;
    float v[8];
    float ss = 0.f;
#pragma unroll
    for (int i = 0; i < 8; i++) { v[i] = ar[lane + 32 * i]; ss += v[i] * v[i]; }
    ss = warp_sum(ss);
    float inv = rsqrtf(ss);
#pragma unroll
    for (int i = 0; i < 8; i++) ar[lane + 32 * i] = v[i] * inv;
}

// ---------------- L2 row normalize + fused denom = dot(q_norm, ksum) + 2n ----------------
__global__ void normdot_kernel(float* __restrict__ a, int N, float nf)
{
    int row = blockIdx.x * 8 + (threadIdx.x >> 5);
    if (row >= N) return;
    int lane = threadIdx.x & 31;
    float* ar = a + (size_t)row * 256;
    float v[8];
    float ss = 0.f;
#pragma unroll
    for (int i = 0; i < 8; i++) { v[i] = ar[lane + 32 * i]; ss += v[i] * v[i]; }
    ss = warp_sum(ss);
    float inv = rsqrtf(ss);
    float ds = 0.f;
#pragma unroll
    for (int i = 0; i < 8; i++) {
        float nq = v[i] * inv;
        ar[lane + 32 * i] = nq;
        ds += nq * d_ksum[lane + 32 * i];
    }
    ds = warp_sum(ds);
    if (lane == 0) d_denom[row] = ds + 2.f * nf;
}

// ---------------- attention epilogue (denom precomputed) ----------------
__global__ void attn_ln_kernel(const float* __restrict__ num,
                               const float* __restrict__ h,
                               const float* __restrict__ g, const float* __restrict__ b,
                               float* __restrict__ out, int N)
{
    int row = blockIdx.x * 8 + (threadIdx.x >> 5);
    if (row >= N) return;
    int lane = threadIdx.x & 31;
    size_t base = (size_t)row * 256;
    float rinv = 1.f / d_denom[row];

    float t[8];
    float s = 0.f;
#pragma unroll
    for (int i = 0; i < 8; i++) {
        int c = lane + 32 * i;
        t[i] = (num[base + c] * rinv + h[base + c]) * 0.5f;
        s += t[i];
    }
    s = warp_sum(s);
    float m = s * (1.f / 256.f);
    float ss = 0.f;
#pragma unroll
    for (int i = 0; i < 8; i++) { float dv = t[i] - m; ss += dv * dv; }
    ss = warp_sum(ss);
    float inv = rsqrtf(ss * (1.f / 256.f) + EPSV);
#pragma unroll
    for (int i = 0; i < 8; i++) {
        int c = lane + 32 * i;
        float r = (t[i] - m) * inv * g[c] + b[c];
        out[base + c] = fmaxf(r, 0.f);
    }
}

// ---------------- BN finalize ----------------
__global__ void bn_finalize_kernel(const float* __restrict__ s1, const float* __restrict__ s2,
                                   const float* __restrict__ g, const float* __restrict__ b,
                                   float* __restrict__ sc, float* __restrict__ sh, float n)
{
    int c = threadIdx.x;
    float m = s1[c] / n;
    float var = s2[c] / n - m * m;
    float scale = g[c] * rsqrtf(var + EPSV);
    sc[c] = scale;
    sh[c] = b[c] - m * scale;
}

// ---------------- BN apply + ReLU ----------------
__global__ void bn_relu_kernel(const float* __restrict__ z, const float* __restrict__ sc,
                               const float* __restrict__ sh, float* __restrict__ out)
{
    size_t i = (size_t)blockIdx.x * blockDim.x + threadIdx.x;
    if (i >= (size_t)NN * 64) return;
    float4 zv = ((const float4*)z)[i];
    int c4 = (int)(i & 63);
    float4 scv = ((const float4*)sc)[c4];
    float4 shv = ((const float4*)sh)[c4];
    float4 o;
    o.x = fmaxf(zv.x * scv.x + shv.x, 0.f);
    o.y = fmaxf(zv.y * scv.y + shv.y, 0.f);
    o.z = fmaxf(zv.z * scv.z + shv.z, 0.f);
    o.w = fmaxf(zv.w * scv.w + shv.w, 0.f);
    ((float4*)out)[i] = o;
}

// ---------------- degree / rsqrt ----------------
__global__ void deg_kernel(const int* __restrict__ col)
{
    int i = blockIdx.x * blockDim.x + threadIdx.x;
    if (i < EE) atomicAdd(&d_deg[col[i]], 1.f);
}

__global__ void rsq_kernel()
{
    int i = blockIdx.x * blockDim.x + threadIdx.x;
    if (i < NN) {
        float dgg = d_deg[i];
        d_rsq[i] = dgg > 0.f ? rsqrtf(dgg) : 0.f;
    }
}

// ---------------- edge scatter ----------------
__global__ void scatter_kernel(const int* __restrict__ rowi, const int* __restrict__ coli,
                               const float* __restrict__ g0, float* __restrict__ agg, int E)
{
    int e = blockIdx.x * 8 + (threadIdx.x >> 5);
    if (e >= E) return;
    int lane = threadIdx.x & 31;
    int r = __ldg(rowi + e);
    int c = __ldg(coli + e);
    float w = d_rsq[c] * d_rsq[r];
    const float4* gr = (const float4*)(g0 + (size_t)r * 256);
    float* ab = agg + (size_t)c * 256;
#pragma unroll
    for (int i = 0; i < 2; i++) {
        float4 gv = gr[lane + 32 * i];
        float* dst = ab + (size_t)(lane + 32 * i) * 4;
        asm volatile("red.global.add.v4.f32 [%0], {%1, %2, %3, %4};"
                     :: "l"(dst), "f"(gv.x * w), "f"(gv.y * w), "f"(gv.z * w), "f"(gv.w * w)
                     : "memory");
    }
}

// ---------------- host ----------------
extern "C" void kernel_launch(void* const* d_in, const int* in_sizes, int n_in,
                              void* d_out, int out_size)
{
    const float* x      = (const float*)d_in[0];
    const int*   ei     = (const int*)d_in[1];
    const float* tW0    = (const float*)d_in[2];
    const float* tb0    = (const float*)d_in[3];
    const float* tln0_g = (const float*)d_in[4];
    const float* tln0_b = (const float*)d_in[5];
    const float* Wq     = (const float*)d_in[6];
    const float* bq     = (const float*)d_in[7];
    const float* Wk     = (const float*)d_in[8];
    const float* bk     = (const float*)d_in[9];
    const float* Wv     = (const float*)d_in[10];
    const float* bv     = (const float*)d_in[11];
    const float* tln1_g = (const float*)d_in[12];
    const float* tln1_b = (const float*)d_in[13];
    const float* gW0    = (const float*)d_in[14];
    const float* gb0    = (const float*)d_in[15];
    const float* gbn0_g = (const float*)d_in[16];
    const float* gbn0_b = (const float*)d_in[17];
    const float* gWc    = (const float*)d_in[18];
    const float* gbc    = (const float*)d_in[19];
    const float* gbn1_g = (const float*)d_in[20];
    const float* gbn1_b = (const float*)d_in[21];
    const float* Wo     = (const float*)d_in[22];
    const float* bo     = (const float*)d_in[23];
    float* out = (float*)d_out;

    float *pz, *pzg, *ph, *pq, *pk, *pv, *pnum, *px1, *pg0, *pagg, *ptail;
    float *pkvs, *pksum, *pvsum;
    float *ps1a, *ps2a, *psc0, *psh0, *ps1b, *ps2b, *psc1, *psh1;
    __nv_bfloat16 *pwth, *pwtl;
    cudaGetSymbolAddress((void**)&pz, d_z);
    cudaGetSymbolAddress((void**)&pzg, d_zg);
    cudaGetSymbolAddress((void**)&ph, d_h);
    cudaGetSymbolAddress((void**)&pq, d_q);
    cudaGetSymbolAddress((void**)&pk, d_k);
    cudaGetSymbolAddress((void**)&pv, d_v);
    cudaGetSymbolAddress((void**)&pnum, d_num);
    cudaGetSymbolAddress((void**)&px1, d_x1);
    cudaGetSymbolAddress((void**)&pg0, d_g0);
    cudaGetSymbolAddress((void**)&pagg, d_agg);
    cudaGetSymbolAddress((void**)&ptail, d_tail);
    cudaGetSymbolAddress((void**)&pkvs, d_kvs);
    cudaGetSymbolAddress((void**)&pksum, d_ksum);
    cudaGetSymbolAddress((void**)&pvsum, d_vsum);
    cudaGetSymbolAddress((void**)&ps1a, d_s1a);
    cudaGetSymbolAddress((void**)&ps2a, d_s2a);
    cudaGetSymbolAddress((void**)&psc0, d_sc0);
    cudaGetSymbolAddress((void**)&psh0, d_sh0);
    cudaGetSymbolAddress((void**)&ps1b, d_s1b);
    cudaGetSymbolAddress((void**)&ps2b, d_s2b);
    cudaGetSymbolAddress((void**)&psc1, d_sc1);
    cudaGetSymbolAddress((void**)&psh1, d_sh1);
    cudaGetSymbolAddress((void**)&pwth, d_wth);
    cudaGetSymbolAddress((void**)&pwtl, d_wtl);

    const int* rowi = ei;
    const int* coli = ei + EE;
    const float nf = (float)NN;

    const int TG_SMEM = 49664;  // 4*10240 (A/B hi/lo) + 8704 (bias panel)
    const int KV_SMEM = 65536;  // max(tiles 34816, epilogue staging 8*2048*4)
    cudaFuncSetAttribute(tgemm_kernel<0>, cudaFuncAttributeMaxDynamicSharedMemorySize, TG_SMEM);
    cudaFuncSetAttribute(tgemm_kernel<1>, cudaFuncAttributeMaxDynamicSharedMemorySize, TG_SMEM);
    cudaFuncSetAttribute(kvs_wmma_kernel, cudaFuncAttributeMaxDynamicSharedMemorySize, KV_SMEM);

    // lazily-created side stream + fork/join events (host resources only; the GPU
    // work enqueued per call is identical every time, so determinism holds)
    static cudaStream_t s_gnn = nullptr;
    static cudaEvent_t ev_fork = nullptr, ev_join = nullptr;
    if (s_gnn == nullptr) {
        cudaStreamCreateWithFlags(&s_gnn, cudaStreamNonBlocking);
        cudaEventCreateWithFlags(&ev_fork, cudaEventDisableTiming);
        cudaEventCreateWithFlags(&ev_join, cudaEventDisableTiming);
    }

    zero_kernel<<<512, 256>>>();

    // weight conversion (transposed hi/lo bf16) — all on main stream before fork
    #define WSL(i) (pwth + (size_t)(i) * 256 * 256), (pwtl + (size_t)(i) * 256 * 256)
    wconv_kernel<<<256, 256>>>(tW0, 256, WSL(0));
    wconv_kernel<<<256, 256>>>(Wq,  256, WSL(1));
    wconv_kernel<<<256, 256>>>(Wk,  256, WSL(2));
    wconv_kernel<<<256, 256>>>(Wv,  256, WSL(3));
    wconv_kernel<<<256, 256>>>(gW0, 256, WSL(4));
    wconv_kernel<<<256, 256>>>(gWc, 256, WSL(5));
    wconv_kernel<<<128, 256>>>(Wo,  128, WSL(6));

    cudaEventRecord(ev_fork, 0);
    cudaStreamWaitEvent(s_gnn, ev_fork, 0);

    dim3 g2((NN + 127) / 128, 2);   // NC=256 GEMMs (R13 proven rasterization)
    dim3 g1((NN + 127) / 128, 1);   // NC=128 GEMM
    int rowgrid = (NN + 7) / 8;

    // ======== GNN branch on side stream (overlaps transformer chain) ========
    deg_kernel<<<(EE + 255) / 256, 256, 0, s_gnn>>>(coli);
    rsq_kernel<<<(NN + 255) / 256, 256, 0, s_gnn>>>();
    tgemm_kernel<0><<<g2, 256, TG_SMEM, s_gnn>>>(x, WSL(4), gb0, 1.f, pzg, NN, NPAD, 256,
                                                 ptail, nullptr, nullptr, nullptr, nullptr);
    colsum2_kernel<<<200, 256, 0, s_gnn>>>(pzg, ps1a, ps2a, NN);
    bn_finalize_kernel<<<1, 256, 0, s_gnn>>>(ps1a, ps2a, gbn0_g, gbn0_b, psc0, psh0, nf);
    bn_relu_kernel<<<25000, 256, 0, s_gnn>>>(pzg, psc0, psh0, pg0);
    scatter_kernel<<<(EE + 7) / 8, 256, 0, s_gnn>>>(rowi, coli, pg0, pagg, EE);
    tgemm_kernel<0><<<g2, 256, TG_SMEM, s_gnn>>>(pagg, WSL(5), gbc, 1.f, pzg, NN, NPAD, 256,
                                                 ptail, nullptr, nullptr, nullptr, nullptr);
    colsum2_kernel<<<200, 256, 0, s_gnn>>>(pzg, ps1b, ps2b, NN);
    bn_finalize_kernel<<<1, 256, 0, s_gnn>>>(ps1b, ps2b, gbn1_g, gbn1_b, psc1, psh1, nf);
    cudaEventRecord(ev_join, s_gnn);

    // ======== Transformer branch on main stream ========
    tgemm_kernel<0><<<g2, 256, TG_SMEM>>>(x, WSL(0), tb0, 1.f, pz, NN, NPAD, 256, ptail,
                                          nullptr, nullptr, nullptr, nullptr);
    ln_relu_kernel<<<rowgrid, 256>>>(pz, tln0_g, tln0_b, ph, NN);
    tgemm_kernel<0><<<g2, 256, TG_SMEM>>>(ph, WSL(1), bq, 1.f, pq, NN, NPAD, 256, ptail,
                                          nullptr, nullptr, nullptr, nullptr);
    tgemm_kernel<0><<<g2, 256, TG_SMEM>>>(ph, WSL(2), bk, 1.f, pk, NN, NPAD, 256, ptail,
                                          nullptr, nullptr, nullptr, nullptr);
    tgemm_kernel<0><<<g2, 256, TG_SMEM>>>(ph, WSL(3), bv, 1.f, pv, NN, NPAD, 256, ptail,
                                          nullptr, nullptr, nullptr, nullptr);
    normalize_kernel<<<rowgrid, 256>>>(pk, NN);
    colsum_kernel<<<200, 256>>>(pk, pksum, NN);
    normdot_kernel<<<rowgrid, 256>>>(pq, NN, nf);     // normalize q + fused denom
    kvs_wmma_kernel<<<dim3(4, (NN + KVCH - 1) / KVCH), 256, KV_SMEM>>>(pk, pv, NN);
    wconv_kernel<<<256, 256>>>(pkvs, 256, WSL(7));
    tgemm_kernel<0><<<g2, 256, TG_SMEM>>>(pq, WSL(7), pvsum, nf, pnum, NN, NPAD, 256, ptail,
                                          nullptr, nullptr, nullptr, nullptr);
    attn_ln_kernel<<<rowgrid, 256>>>(pnum, ph, tln1_g, tln1_b, px1, NN);

    // ======== join + output head (combine fused into final GEMM, MODE=1) ========
    cudaStreamWaitEvent(0, ev_join, 0);
    tgemm_kernel<1><<<g1, 256, TG_SMEM>>>(pzg, WSL(6), bo, 1.f, out, NN, NN, 128, ptail,
                                          pg0, px1, psc1, psh1);
}